// round 11
// baseline (speedup 1.0000x reference)
#include <cuda_runtime.h>
#include <cstdint>
#include <math.h>

// ----------------------------------------------------------------------------
// DLRM forward: bottom MLP (13->512->256->64, ReLU) ; 26-table embedding bag
// (sum-pool, L=10, D=64) ; dot interaction (27x27 lower tri, 351 pairs) ;
// top MLP (415->512->256->1, ReLU/ReLU/Sigmoid).
//
// GEMMs: m16n8k8 TF32 tensor-core MMA, 2-term hi/lo split ("3xTF32") for
// fp32-class accuracy. This round: (a) register-prefetch software pipeline in
// the GEMM k-loop to hide global-load latency behind the MMA section;
// (b) embedding-bag blocks fused into the three bottom-MLP launches as extra
// grid blocks so the DRAM-bound gather overlaps the latency-bound GEMMs.
// ----------------------------------------------------------------------------

#define BB      8192        // batch
#define NTAB    26
#define LBAG    10
#define VROWS   200000
#define DD      64
#define TROW    1728        // 27*64 floats per batch row of T
#define RLD     416         // padded row stride of R (415 used)
#define NEMB    (NTAB * (BB / 16))   // 13312 embed blocks total (16 bags each)

// ---------------- scratch (device globals: no allocs allowed) ----------------
__device__ __align__(16) float g_h1[BB * 512];   // bot1 out / top1 out (z1)
__device__ __align__(16) float g_h2[BB * 256];   // bot2 out / top2 out (z2)
__device__ __align__(16) float g_T [BB * TROW];  // [B][27][64]: row0 = h, rows 1..26 = pooled
__device__ __align__(16) float g_R [BB * RLD];   // [B][416]: cols 0..63 = h, 64..414 = tril dots
__device__ int g_idx64;                           // 1 if lS_i is int64, 0 if int32

// ---------------- helpers ----------------
__device__ __forceinline__ uint32_t f2tf32(float x) {
    uint32_t r;
    asm("cvt.rna.tf32.f32 %0, %1;" : "=r"(r) : "f"(x));
    return r;
}

__device__ __forceinline__ void mma_tf32(float* d, const uint32_t* a, const uint32_t* b) {
    asm volatile(
        "mma.sync.aligned.m16n8k8.row.col.f32.tf32.tf32.f32 "
        "{%0,%1,%2,%3}, {%4,%5,%6,%7}, {%8,%9}, {%0,%1,%2,%3};\n"
        : "+f"(d[0]), "+f"(d[1]), "+f"(d[2]), "+f"(d[3])
        : "r"(a[0]), "r"(a[1]), "r"(a[2]), "r"(a[3]), "r"(b[0]), "r"(b[1]));
}

// ---------------- index-width autodetect ----------------
__global__ void detect_idx_kernel(const unsigned int* __restrict__ p) {
    if (threadIdx.x == 0 && blockIdx.x == 0) {
        int f = 1;
        for (int i = 0; i < 128; i++) {
            if (p[2 * i + 1] != 0u) { f = 0; break; }
        }
        g_idx64 = f;
    }
}

// ---------------- embedding bag block (device side) -------------------------
// One "embed block" = 256 threads = 16 bags x 16 float4-columns for table t.
__device__ __forceinline__ void embed_block(int e, const void* __restrict__ lSi,
                                            const float* __restrict__ emb)
{
    const int c   = threadIdx.x & 15;          // float4 column
    const int bag = threadIdx.x >> 4;          // 0..15
    const int t   = e >> 9;                    // table (512 blocks per table)
    const int b   = ((e & 511) << 4) + bag;

    const float4* tab = reinterpret_cast<const float4*>(emb)
                      + (size_t)t * (size_t)(VROWS * (DD / 4));
    const long long ibase = (long long)t * (BB * LBAG) + (long long)b * LBAG;

    int idx[LBAG];
    if (g_idx64) {
        const long long* I = reinterpret_cast<const long long*>(lSi);
        #pragma unroll
        for (int j = 0; j < LBAG; j++) idx[j] = (int)I[ibase + j];
    } else {
        const int* I = reinterpret_cast<const int*>(lSi);
        #pragma unroll
        for (int j = 0; j < LBAG; j++) idx[j] = I[ibase + j];
    }

    float4 acc = make_float4(0.f, 0.f, 0.f, 0.f);
    #pragma unroll
    for (int j = 0; j < LBAG; j++) {
        const float4 v = __ldg(&tab[(size_t)idx[j] * (DD / 4) + c]);
        acc.x += v.x; acc.y += v.y; acc.z += v.z; acc.w += v.w;
    }
    reinterpret_cast<float4*>(g_T)[(size_t)b * (TROW / 4) + (1 + t) * (DD / 4) + c] = acc;
}

// ---------------- fused GEMM (+ optional embed blocks) ----------------------
// GEMM: C = relu(A[8192,K] @ W[M,K]^T + bias). Block tile 128x64, BK=16,
// 256 threads = 8 warps (4m x 2n), warp tile 32x32. Register-prefetch
// pipeline: next k-tile is loaded into registers while the current tile's
// MMAs run, hiding L2/DRAM latency.
// Blocks with blockIdx.x >= nGemm run embedding-bag work instead.
__global__ __launch_bounds__(256)
void fused_gemm_embed(const float* __restrict__ A, int lda,
                      const float* __restrict__ W, int K,
                      const float* __restrict__ bias,
                      float* __restrict__ C, int ldc,
                      int gridGx, int nGemm,
                      const void* __restrict__ lSi,
                      const float* __restrict__ emb,
                      int embBase)
{
    if ((int)blockIdx.x >= nGemm) {
        embed_block((int)blockIdx.x - nGemm + embBase, lSi, emb);
        return;
    }

    __shared__ uint32_t Ah[128][17];
    __shared__ uint32_t Al[128][17];
    __shared__ uint32_t Wh[64][17];
    __shared__ uint32_t Wl[64][17];

    const int tid  = threadIdx.x;
    const int kld  = tid & 15;        // k slot this thread loads
    const int mth  = tid >> 4;        // 0..15: base m/n slot this thread loads
    const int warp = tid >> 5;
    const int lane = tid & 31;
    const int wm   = warp & 3;        // 0..3
    const int wn   = warp >> 2;       // 0..1
    const int gid  = lane >> 2;       // 0..7
    const int tig  = lane & 3;        // 0..3

    const int bx = (int)blockIdx.x % gridGx;
    const int by = (int)blockIdx.x / gridGx;
    const long long rowBase = (long long)by * 128;
    const int colBase = bx * 64;

    float acc[2][4][4];
    #pragma unroll
    for (int mt = 0; mt < 2; mt++)
        #pragma unroll
        for (int nt = 0; nt < 4; nt++)
            #pragma unroll
            for (int q = 0; q < 4; q++) acc[mt][nt][q] = 0.0f;

    // ---- prologue: load k-tile 0 into registers ----
    float aR[8], wR[4];
    {
        const int gk = kld;
        const bool kin = (gk < K);
        #pragma unroll
        for (int i = 0; i < 8; i++) {
            const int m = mth + 16 * i;
            aR[i] = kin ? __ldg(&A[(rowBase + m) * (long long)lda + gk]) : 0.0f;
        }
        #pragma unroll
        for (int i = 0; i < 4; i++) {
            const int n = mth + 16 * i;
            wR[i] = kin ? __ldg(&W[(size_t)(colBase + n) * (size_t)K + gk]) : 0.0f;
        }
    }

    for (int k0 = 0; k0 < K; k0 += 16) {
        // ---- store current tile (with hi/lo split) to smem ----
        #pragma unroll
        for (int i = 0; i < 8; i++) {
            const int m = mth + 16 * i;
            const uint32_t hi = f2tf32(aR[i]);
            Ah[m][kld] = hi;
            Al[m][kld] = f2tf32(aR[i] - __uint_as_float(hi));
        }
        #pragma unroll
        for (int i = 0; i < 4; i++) {
            const int n = mth + 16 * i;
            const uint32_t hi = f2tf32(wR[i]);
            Wh[n][kld] = hi;
            Wl[n][kld] = f2tf32(wR[i] - __uint_as_float(hi));
        }
        __syncthreads();

        // ---- prefetch next k-tile into registers (overlaps the MMAs) ----
        if (k0 + 16 < K) {
            const int gk = k0 + 16 + kld;
            const bool kin = (gk < K);
            #pragma unroll
            for (int i = 0; i < 8; i++) {
                const int m = mth + 16 * i;
                aR[i] = kin ? __ldg(&A[(rowBase + m) * (long long)lda + gk]) : 0.0f;
            }
            #pragma unroll
            for (int i = 0; i < 4; i++) {
                const int n = mth + 16 * i;
                wR[i] = kin ? __ldg(&W[(size_t)(colBase + n) * (size_t)K + gk]) : 0.0f;
            }
        }

        // ---- MMA section ----
        #pragma unroll
        for (int kk = 0; kk < 2; kk++) {
            const int ks = kk * 8;
            uint32_t a_hi[2][4], a_lo[2][4];
            #pragma unroll
            for (int mt = 0; mt < 2; mt++) {
                const int r = wm * 32 + mt * 16 + gid;
                a_hi[mt][0] = Ah[r    ][ks + tig];
                a_hi[mt][1] = Ah[r + 8][ks + tig];
                a_hi[mt][2] = Ah[r    ][ks + tig + 4];
                a_hi[mt][3] = Ah[r + 8][ks + tig + 4];
                a_lo[mt][0] = Al[r    ][ks + tig];
                a_lo[mt][1] = Al[r + 8][ks + tig];
                a_lo[mt][2] = Al[r    ][ks + tig + 4];
                a_lo[mt][3] = Al[r + 8][ks + tig + 4];
            }
            uint32_t b_hi[4][2], b_lo[4][2];
            #pragma unroll
            for (int nt = 0; nt < 4; nt++) {
                const int n = wn * 32 + nt * 8 + gid;
                b_hi[nt][0] = Wh[n][ks + tig];
                b_hi[nt][1] = Wh[n][ks + tig + 4];
                b_lo[nt][0] = Wl[n][ks + tig];
                b_lo[nt][1] = Wl[n][ks + tig + 4];
            }
            #pragma unroll
            for (int mt = 0; mt < 2; mt++)
                #pragma unroll
                for (int nt = 0; nt < 4; nt++) {
                    mma_tf32(acc[mt][nt], a_hi[mt], b_hi[nt]);
                    mma_tf32(acc[mt][nt], a_hi[mt], b_lo[nt]);
                    mma_tf32(acc[mt][nt], a_lo[mt], b_hi[nt]);
                }
        }
        __syncthreads();
    }

    // ---- epilogue: bias + relu, float2 stores ----
    #pragma unroll
    for (int mt = 0; mt < 2; mt++)
        #pragma unroll
        for (int nt = 0; nt < 4; nt++) {
            const long long row = rowBase + wm * 32 + mt * 16 + gid;
            const int col = colBase + wn * 32 + nt * 8 + 2 * tig;
            const float b0 = bias[col];
            const float b1 = bias[col + 1];
            float2 v01, v23;
            v01.x = fmaxf(acc[mt][nt][0] + b0, 0.0f);
            v01.y = fmaxf(acc[mt][nt][1] + b1, 0.0f);
            v23.x = fmaxf(acc[mt][nt][2] + b0, 0.0f);
            v23.y = fmaxf(acc[mt][nt][3] + b1, 0.0f);
            *reinterpret_cast<float2*>(&C[row * ldc + col])       = v01;
            *reinterpret_cast<float2*>(&C[(row + 8) * ldc + col]) = v23;
        }
}

// ---------------- dot interaction: R[b] = [h(64), tril dots(351)] -----------
__global__ void interact_kernel()
{
    __shared__ __align__(16) float Ts[TROW];
    const int b = blockIdx.x;
    const float4* Tb = reinterpret_cast<const float4*>(g_T + (size_t)b * TROW);
    float4* Ts4 = reinterpret_cast<float4*>(Ts);
    for (int i = threadIdx.x; i < TROW / 4; i += 128) Ts4[i] = Tb[i];
    __syncthreads();

    float* Rb = g_R + (size_t)b * RLD;
    if (threadIdx.x < 64) Rb[threadIdx.x] = Ts[threadIdx.x];   // copy h

    for (int p = threadIdx.x; p < 351; p += 128) {
        // invert p -> (i, j): p = i*(i-1)/2 + j, j < i  (tril row-major order)
        int i = (int)((1.0f + sqrtf(1.0f + 8.0f * (float)p)) * 0.5f);
        while (i * (i - 1) / 2 > p) --i;
        while ((i + 1) * i / 2 <= p) ++i;
        const int j = p - i * (i - 1) / 2;

        const float4* ri = Ts4 + i * (DD / 4);
        const float4* rj = Ts4 + j * (DD / 4);
        float s = 0.0f;
        #pragma unroll
        for (int k = 0; k < DD / 4; k++) {
            const float4 u = ri[k];
            const float4 v = rj[k];
            s += u.x * v.x + u.y * v.y + u.z * v.z + u.w * v.w;
        }
        Rb[64 + p] = s;
    }
}

// ---------------- top layer 3: out[b] = sigmoid(dot(z2[b], w3) + b3) --------
__global__ void top3_kernel(const float* __restrict__ w3, const float* __restrict__ b3,
                            float* __restrict__ out)
{
    const int gwarp = (int)((blockIdx.x * blockDim.x + threadIdx.x) >> 5);  // batch row
    const int lane  = threadIdx.x & 31;
    const float4* z = reinterpret_cast<const float4*>(g_h2) + (size_t)gwarp * 64;
    const float4* w = reinterpret_cast<const float4*>(w3);

    const float4 z0 = z[lane],      w0 = w[lane];
    const float4 z1 = z[lane + 32], w1 = w[lane + 32];
    float s = z0.x * w0.x + z0.y * w0.y + z0.z * w0.z + z0.w * w0.w
            + z1.x * w1.x + z1.y * w1.y + z1.z * w1.z + z1.w * w1.w;
    #pragma unroll
    for (int o = 16; o > 0; o >>= 1) s += __shfl_xor_sync(0xffffffffu, s, o);
    if (lane == 0) out[gwarp] = 1.0f / (1.0f + expf(-(s + b3[0])));
}

// ---------------- host ----------------
static void run_fused(const float* A, int lda, const float* W, int K,
                      const float* bias, float* C, int ldc, int M,
                      const void* lSi, const float* emb, int embBase, int embCount)
{
    const int gridGx = M / 64;
    const int nGemm  = gridGx * (BB / 128);
    fused_gemm_embed<<<nGemm + embCount, 256>>>(A, lda, W, K, bias, C, ldc,
                                                gridGx, nGemm, lSi, emb, embBase);
}

extern "C" void kernel_launch(void* const* d_in, const int* in_sizes, int n_in,
                              void* d_out, int out_size)
{
    // --- input-order autodetect: insertion order (x first) vs alphabetical ---
    int IX_X, IX_LSI, IX_EMB, IX_BW1, IX_BB1, IX_BW2, IX_BB2, IX_BW3, IX_BB3;
    int IX_TW1, IX_TB1, IX_TW2, IX_TB2, IX_TW3, IX_TB3;
    if (in_sizes[0] == BB * 13) {
        IX_X = 0; IX_LSI = 1; IX_EMB = 3;
        IX_BW1 = 4;  IX_BB1 = 5;  IX_BW2 = 6;  IX_BB2 = 7;  IX_BW3 = 8;  IX_BB3 = 9;
        IX_TW1 = 10; IX_TB1 = 11; IX_TW2 = 12; IX_TB2 = 13; IX_TW3 = 14; IX_TB3 = 15;
    } else {
        IX_BW1 = 0; IX_BW2 = 1; IX_BW3 = 2; IX_BB1 = 3; IX_BB2 = 4; IX_BB3 = 5;
        IX_EMB = 6; IX_LSI = 7;
        IX_TW1 = 9; IX_TW2 = 10; IX_TW3 = 11; IX_TB1 = 12; IX_TB2 = 13; IX_TB3 = 14;
        IX_X = 15;
    }

    const float* x    = (const float*)d_in[IX_X];
    const void*  lSi  = d_in[IX_LSI];
    const float* emb  = (const float*)d_in[IX_EMB];
    const float* bw1  = (const float*)d_in[IX_BW1];
    const float* bb1  = (const float*)d_in[IX_BB1];
    const float* bw2  = (const float*)d_in[IX_BW2];
    const float* bb2  = (const float*)d_in[IX_BB2];
    const float* bw3  = (const float*)d_in[IX_BW3];
    const float* bb3  = (const float*)d_in[IX_BB3];
    const float* tw1  = (const float*)d_in[IX_TW1];
    const float* tb1  = (const float*)d_in[IX_TB1];
    const float* tw2  = (const float*)d_in[IX_TW2];
    const float* tb2  = (const float*)d_in[IX_TB2];
    const float* tw3  = (const float*)d_in[IX_TW3];
    const float* tb3  = (const float*)d_in[IX_TB3];
    float* out = (float*)d_out;

    float *h1, *h2, *T, *R;
    cudaGetSymbolAddress((void**)&h1, g_h1);
    cudaGetSymbolAddress((void**)&h2, g_h2);
    cudaGetSymbolAddress((void**)&T,  g_T);
    cudaGetSymbolAddress((void**)&R,  g_R);

    // 0) detect index width (deterministic: depends only on input data)
    detect_idx_kernel<<<1, 32>>>((const unsigned int*)lSi);

    // 1) bottom MLP fused with embedding-bag blocks (embed split ~evenly
    //    across the three launches; all NEMB blocks done by end of bot3)
    const int E1 = 4438, E2 = 4437, E3 = NEMB - 4438 - 4437;  // 13312 total
    run_fused(x,  13,  bw1, 13,  bb1, h1, 512, 512, lSi, emb, 0,        E1);
    run_fused(h1, 512, bw2, 512, bb2, h2, 256, 256, lSi, emb, E1,       E2);
    run_fused(h2, 256, bw3, 256, bb3, T,  TROW, 64, lSi, emb, E1 + E2,  E3);

    // 2) dot interaction -> R[b][0..414]
    interact_kernel<<<BB, 128>>>();

    // 3) top MLP: 415 -> 512 -> 256 (ReLU), reuse h1/h2 as z1/z2
    run_fused(R,  RLD, tw1, 415, tb1, h1, 512, 512, lSi, emb, 0, 0);
    run_fused(h1, 512, tw2, 512, tb2, h2, 256, 256, lSi, emb, 0, 0);

    // 4) final 256 -> 1 dot + sigmoid
    top3_kernel<<<BB / 8, 256>>>(tw3, tb3, out);
}

// round 12
// speedup vs baseline: 1.5255x; 1.5255x over previous
#include <cuda_runtime.h>
#include <cstdint>
#include <math.h>

// ----------------------------------------------------------------------------
// DLRM forward: bottom MLP (13->512->256->64, ReLU) ; 26-table embedding bag
// (sum-pool, L=10, D=64) ; dot interaction (27x27 lower tri, 351 pairs) ;
// top MLP (415->512->256->1, ReLU/ReLU/Sigmoid).
//
// GEMMs: m16n8k8 TF32 MMA, 2-term hi/lo split ("3xTF32") for fp32 accuracy.
// R11->R12: (a) interact smem rows padded to 68 floats -> kills the 8-way
// bank conflicts ((64i+4k)%32 was i-independent); (b) GEMM double-buffered
// smem with ONE sync per k-iter and split-at-consume (single fp32 smem copy),
// so the global prefetch truly overlaps the MMA section.
// ----------------------------------------------------------------------------

#define BB      8192
#define NTAB    26
#define LBAG    10
#define VROWS   200000
#define DD      64
#define TROW    1728        // 27*64 floats per batch row of T (global, unpadded)
#define RLD     416         // padded row stride of R (415 used)
#define NEMB    (NTAB * (BB / 16))   // 13312 embed blocks (16 bags each)

// ---------------- scratch (device globals: no allocs allowed) ----------------
__device__ __align__(16) float g_h1[BB * 512];
__device__ __align__(16) float g_h2[BB * 256];
__device__ __align__(16) float g_T [BB * TROW];
__device__ __align__(16) float g_R [BB * RLD];
__device__ int g_idx64;

// ---------------- helpers ----------------
__device__ __forceinline__ uint32_t f2tf32(float x) {
    uint32_t r;
    asm("cvt.rna.tf32.f32 %0, %1;" : "=r"(r) : "f"(x));
    return r;
}

__device__ __forceinline__ void mma_tf32(float* d, const uint32_t* a, const uint32_t* b) {
    asm volatile(
        "mma.sync.aligned.m16n8k8.row.col.f32.tf32.tf32.f32 "
        "{%0,%1,%2,%3}, {%4,%5,%6,%7}, {%8,%9}, {%0,%1,%2,%3};\n"
        : "+f"(d[0]), "+f"(d[1]), "+f"(d[2]), "+f"(d[3])
        : "r"(a[0]), "r"(a[1]), "r"(a[2]), "r"(a[3]), "r"(b[0]), "r"(b[1]));
}

// ---------------- index-width autodetect ----------------
__global__ void detect_idx_kernel(const unsigned int* __restrict__ p) {
    if (threadIdx.x == 0 && blockIdx.x == 0) {
        int f = 1;
        for (int i = 0; i < 128; i++) {
            if (p[2 * i + 1] != 0u) { f = 0; break; }
        }
        g_idx64 = f;
    }
}

// ---------------- embedding bag block (device side) -------------------------
__device__ __forceinline__ void embed_block(int e, const void* __restrict__ lSi,
                                            const float* __restrict__ emb)
{
    const int c   = threadIdx.x & 15;
    const int bag = threadIdx.x >> 4;
    const int t   = e >> 9;
    const int b   = ((e & 511) << 4) + bag;

    const float4* tab = reinterpret_cast<const float4*>(emb)
                      + (size_t)t * (size_t)(VROWS * (DD / 4));
    const long long ibase = (long long)t * (BB * LBAG) + (long long)b * LBAG;

    int idx[LBAG];
    if (g_idx64) {
        const long long* I = reinterpret_cast<const long long*>(lSi);
        #pragma unroll
        for (int j = 0; j < LBAG; j++) idx[j] = (int)I[ibase + j];
    } else {
        const int* I = reinterpret_cast<const int*>(lSi);
        #pragma unroll
        for (int j = 0; j < LBAG; j++) idx[j] = I[ibase + j];
    }

    float4 acc = make_float4(0.f, 0.f, 0.f, 0.f);
    #pragma unroll
    for (int j = 0; j < LBAG; j++) {
        const float4 v = __ldg(&tab[(size_t)idx[j] * (DD / 4) + c]);
        acc.x += v.x; acc.y += v.y; acc.z += v.z; acc.w += v.w;
    }
    reinterpret_cast<float4*>(g_T)[(size_t)b * (TROW / 4) + (1 + t) * (DD / 4) + c] = acc;
}

// ---------------- fused GEMM (+ optional embed blocks) ----------------------
// C = relu(A[8192,K] @ W[M,K]^T + bias). Block tile 128x64, BK=16, 256 thr =
// 8 warps (4m x 2n), warp tile 32x32. Double-buffered fp32 smem, ONE sync per
// k-iter; hi/lo TF32 split happens at fragment load (registers).
__global__ __launch_bounds__(256)
void fused_gemm_embed(const float* __restrict__ A, int lda,
                      const float* __restrict__ W, int K,
                      const float* __restrict__ bias,
                      float* __restrict__ C, int ldc,
                      int gridGx, int nGemm,
                      const void* __restrict__ lSi,
                      const float* __restrict__ emb,
                      int embBase)
{
    if ((int)blockIdx.x >= nGemm) {
        embed_block((int)blockIdx.x - nGemm + embBase, lSi, emb);
        return;
    }

    __shared__ float As[2][128][17];
    __shared__ float Ws[2][64][17];

    const int tid  = threadIdx.x;
    const int kld  = tid & 15;
    const int mth  = tid >> 4;
    const int warp = tid >> 5;
    const int lane = tid & 31;
    const int wm   = warp & 3;
    const int wn   = warp >> 2;
    const int gid  = lane >> 2;
    const int tig  = lane & 3;

    const int bx = (int)blockIdx.x % gridGx;
    const int by = (int)blockIdx.x / gridGx;
    const long long rowBase = (long long)by * 128;
    const int colBase = bx * 64;

    float acc[2][4][4];
    #pragma unroll
    for (int mt = 0; mt < 2; mt++)
        #pragma unroll
        for (int nt = 0; nt < 4; nt++)
            #pragma unroll
            for (int q = 0; q < 4; q++) acc[mt][nt][q] = 0.0f;

    float aR[8], wR[4];

    // ---- prologue: load k-tile 0 -> regs -> smem stage 0 ----
    {
        const int gk = kld;
        const bool kin = (gk < K);
        #pragma unroll
        for (int i = 0; i < 8; i++) {
            const int m = mth + 16 * i;
            aR[i] = kin ? __ldg(&A[(rowBase + m) * (long long)lda + gk]) : 0.0f;
        }
        #pragma unroll
        for (int i = 0; i < 4; i++) {
            const int n = mth + 16 * i;
            wR[i] = kin ? __ldg(&W[(size_t)(colBase + n) * (size_t)K + gk]) : 0.0f;
        }
        #pragma unroll
        for (int i = 0; i < 8; i++) As[0][mth + 16 * i][kld] = aR[i];
        #pragma unroll
        for (int i = 0; i < 4; i++) Ws[0][mth + 16 * i][kld] = wR[i];
    }
    __syncthreads();

    int s = 0;
    for (int k0 = 0; k0 < K; k0 += 16) {
        const bool more = (k0 + 16) < K;

        // ---- prefetch next k-tile into registers (overlaps MMAs below) ----
        if (more) {
            const int gk = k0 + 16 + kld;
            const bool kin = (gk < K);
            #pragma unroll
            for (int i = 0; i < 8; i++) {
                const int m = mth + 16 * i;
                aR[i] = kin ? __ldg(&A[(rowBase + m) * (long long)lda + gk]) : 0.0f;
            }
            #pragma unroll
            for (int i = 0; i < 4; i++) {
                const int n = mth + 16 * i;
                wR[i] = kin ? __ldg(&W[(size_t)(colBase + n) * (size_t)K + gk]) : 0.0f;
            }
        }

        // ---- MMA section on stage s (split hi/lo at fragment load) ----
        #pragma unroll
        for (int kk = 0; kk < 2; kk++) {
            const int ks = kk * 8;
            uint32_t a_hi[2][4], a_lo[2][4];
            #pragma unroll
            for (int mt = 0; mt < 2; mt++) {
                const int r = wm * 32 + mt * 16 + gid;
                const float f0 = As[s][r    ][ks + tig];
                const float f1 = As[s][r + 8][ks + tig];
                const float f2 = As[s][r    ][ks + tig + 4];
                const float f3 = As[s][r + 8][ks + tig + 4];
                a_hi[mt][0] = f2tf32(f0); a_lo[mt][0] = f2tf32(f0 - __uint_as_float(a_hi[mt][0]));
                a_hi[mt][1] = f2tf32(f1); a_lo[mt][1] = f2tf32(f1 - __uint_as_float(a_hi[mt][1]));
                a_hi[mt][2] = f2tf32(f2); a_lo[mt][2] = f2tf32(f2 - __uint_as_float(a_hi[mt][2]));
                a_hi[mt][3] = f2tf32(f3); a_lo[mt][3] = f2tf32(f3 - __uint_as_float(a_hi[mt][3]));
            }
            uint32_t b_hi[4][2], b_lo[4][2];
            #pragma unroll
            for (int nt = 0; nt < 4; nt++) {
                const int n = wn * 32 + nt * 8 + gid;
                const float g0 = Ws[s][n][ks + tig];
                const float g1 = Ws[s][n][ks + tig + 4];
                b_hi[nt][0] = f2tf32(g0); b_lo[nt][0] = f2tf32(g0 - __uint_as_float(b_hi[nt][0]));
                b_hi[nt][1] = f2tf32(g1); b_lo[nt][1] = f2tf32(g1 - __uint_as_float(b_hi[nt][1]));
            }
            #pragma unroll
            for (int mt = 0; mt < 2; mt++)
                #pragma unroll
                for (int nt = 0; nt < 4; nt++) {
                    mma_tf32(acc[mt][nt], a_hi[mt], b_hi[nt]);
                    mma_tf32(acc[mt][nt], a_hi[mt], b_lo[nt]);
                    mma_tf32(acc[mt][nt], a_lo[mt], b_hi[nt]);
                }
        }

        // ---- store prefetched tile into the other stage ----
        if (more) {
            #pragma unroll
            for (int i = 0; i < 8; i++) As[s ^ 1][mth + 16 * i][kld] = aR[i];
            #pragma unroll
            for (int i = 0; i < 4; i++) Ws[s ^ 1][mth + 16 * i][kld] = wR[i];
        }
        __syncthreads();   // single barrier: protects both read-done and write-visible
        s ^= 1;
    }

    // ---- epilogue: bias + relu, float2 stores ----
    #pragma unroll
    for (int mt = 0; mt < 2; mt++)
        #pragma unroll
        for (int nt = 0; nt < 4; nt++) {
            const long long row = rowBase + wm * 32 + mt * 16 + gid;
            const int col = colBase + wn * 32 + nt * 8 + 2 * tig;
            const float b0 = bias[col];
            const float b1 = bias[col + 1];
            float2 v01, v23;
            v01.x = fmaxf(acc[mt][nt][0] + b0, 0.0f);
            v01.y = fmaxf(acc[mt][nt][1] + b1, 0.0f);
            v23.x = fmaxf(acc[mt][nt][2] + b0, 0.0f);
            v23.y = fmaxf(acc[mt][nt][3] + b1, 0.0f);
            *reinterpret_cast<float2*>(&C[row * ldc + col])       = v01;
            *reinterpret_cast<float2*>(&C[(row + 8) * ldc + col]) = v23;
        }
}

// ---------------- dot interaction: R[b] = [h(64), tril dots(351)] -----------
// Smem rows padded to 17 float4 (68 floats): bank group of row i, col k is
// (4i+4k)%32 -> rj lanes (consecutive j) hit distinct banks; same-i ri lanes
// hit the SAME address (broadcast). Previous layout was 8-way conflicted.
__global__ void interact_kernel()
{
    __shared__ __align__(16) float Ts[27 * 68];
    const int b = blockIdx.x;
    const float4* Tb = reinterpret_cast<const float4*>(g_T + (size_t)b * TROW);
    float4* Ts4 = reinterpret_cast<float4*>(Ts);

    for (int g = threadIdx.x; g < TROW / 4; g += 128) {
        const int r = g >> 4;        // row 0..26
        const int c = g & 15;        // float4 col 0..15
        Ts4[r * 17 + c] = Tb[g];
    }
    __syncthreads();

    float* Rb = g_R + (size_t)b * RLD;
    if (threadIdx.x < 64) Rb[threadIdx.x] = Ts[threadIdx.x];   // row 0 = h

    for (int p = threadIdx.x; p < 351; p += 128) {
        int i = (int)((1.0f + sqrtf(1.0f + 8.0f * (float)p)) * 0.5f);
        while (i * (i - 1) / 2 > p) --i;
        while ((i + 1) * i / 2 <= p) ++i;
        const int j = p - i * (i - 1) / 2;

        const float4* ri = Ts4 + i * 17;
        const float4* rj = Ts4 + j * 17;
        float s = 0.0f;
        #pragma unroll
        for (int k = 0; k < DD / 4; k++) {
            const float4 u = ri[k];
            const float4 v = rj[k];
            s += u.x * v.x + u.y * v.y + u.z * v.z + u.w * v.w;
        }
        Rb[64 + p] = s;
    }
}

// ---------------- top layer 3: out[b] = sigmoid(dot(z2[b], w3) + b3) --------
__global__ void top3_kernel(const float* __restrict__ w3, const float* __restrict__ b3,
                            float* __restrict__ out)
{
    const int gwarp = (int)((blockIdx.x * blockDim.x + threadIdx.x) >> 5);
    const int lane  = threadIdx.x & 31;
    const float4* z = reinterpret_cast<const float4*>(g_h2) + (size_t)gwarp * 64;
    const float4* w = reinterpret_cast<const float4*>(w3);

    const float4 z0 = z[lane],      w0 = w[lane];
    const float4 z1 = z[lane + 32], w1 = w[lane + 32];
    float s = z0.x * w0.x + z0.y * w0.y + z0.z * w0.z + z0.w * w0.w
            + z1.x * w1.x + z1.y * w1.y + z1.z * w1.z + z1.w * w1.w;
    #pragma unroll
    for (int o = 16; o > 0; o >>= 1) s += __shfl_xor_sync(0xffffffffu, s, o);
    if (lane == 0) out[gwarp] = 1.0f / (1.0f + expf(-(s + b3[0])));
}

// ---------------- host ----------------
static void run_fused(const float* A, int lda, const float* W, int K,
                      const float* bias, float* C, int ldc, int M,
                      const void* lSi, const float* emb, int embBase, int embCount)
{
    const int gridGx = M / 64;
    const int nGemm  = gridGx * (BB / 128);
    fused_gemm_embed<<<nGemm + embCount, 256>>>(A, lda, W, K, bias, C, ldc,
                                                gridGx, nGemm, lSi, emb, embBase);
}

extern "C" void kernel_launch(void* const* d_in, const int* in_sizes, int n_in,
                              void* d_out, int out_size)
{
    int IX_X, IX_LSI, IX_EMB, IX_BW1, IX_BB1, IX_BW2, IX_BB2, IX_BW3, IX_BB3;
    int IX_TW1, IX_TB1, IX_TW2, IX_TB2, IX_TW3, IX_TB3;
    if (in_sizes[0] == BB * 13) {
        IX_X = 0; IX_LSI = 1; IX_EMB = 3;
        IX_BW1 = 4;  IX_BB1 = 5;  IX_BW2 = 6;  IX_BB2 = 7;  IX_BW3 = 8;  IX_BB3 = 9;
        IX_TW1 = 10; IX_TB1 = 11; IX_TW2 = 12; IX_TB2 = 13; IX_TW3 = 14; IX_TB3 = 15;
    } else {
        IX_BW1 = 0; IX_BW2 = 1; IX_BW3 = 2; IX_BB1 = 3; IX_BB2 = 4; IX_BB3 = 5;
        IX_EMB = 6; IX_LSI = 7;
        IX_TW1 = 9; IX_TW2 = 10; IX_TW3 = 11; IX_TB1 = 12; IX_TB2 = 13; IX_TB3 = 14;
        IX_X = 15;
    }

    const float* x    = (const float*)d_in[IX_X];
    const void*  lSi  = d_in[IX_LSI];
    const float* emb  = (const float*)d_in[IX_EMB];
    const float* bw1  = (const float*)d_in[IX_BW1];
    const float* bb1  = (const float*)d_in[IX_BB1];
    const float* bw2  = (const float*)d_in[IX_BW2];
    const float* bb2  = (const float*)d_in[IX_BB2];
    const float* bw3  = (const float*)d_in[IX_BW3];
    const float* bb3  = (const float*)d_in[IX_BB3];
    const float* tw1  = (const float*)d_in[IX_TW1];
    const float* tb1  = (const float*)d_in[IX_TB1];
    const float* tw2  = (const float*)d_in[IX_TW2];
    const float* tb2  = (const float*)d_in[IX_TB2];
    const float* tw3  = (const float*)d_in[IX_TW3];
    const float* tb3  = (const float*)d_in[IX_TB3];
    float* out = (float*)d_out;

    float *h1, *h2, *T, *R;
    cudaGetSymbolAddress((void**)&h1, g_h1);
    cudaGetSymbolAddress((void**)&h2, g_h2);
    cudaGetSymbolAddress((void**)&T,  g_T);
    cudaGetSymbolAddress((void**)&R,  g_R);

    detect_idx_kernel<<<1, 32>>>((const unsigned int*)lSi);

    // bottom MLP fused with embedding-bag blocks
    const int E1 = 4438, E2 = 4437, E3 = NEMB - 4438 - 4437;
    run_fused(x,  13,  bw1, 13,  bb1, h1, 512, 512, lSi, emb, 0,       E1);
    run_fused(h1, 512, bw2, 512, bb2, h2, 256, 256, lSi, emb, E1,      E2);
    run_fused(h2, 256, bw3, 256, bb3, T,  TROW, 64, lSi, emb, E1 + E2, E3);

    // dot interaction
    interact_kernel<<<BB, 128>>>();

    // top MLP
    run_fused(R,  RLD, tw1, 415, tb1, h1, 512, 512, lSi, emb, 0, 0);
    run_fused(h1, 512, tw2, 512, tb2, h2, 256, 256, lSi, emb, 0, 0);

    // final 256 -> 1 dot + sigmoid
    top3_kernel<<<BB / 8, 256>>>(tw3, tb3, out);
}

// round 13
// speedup vs baseline: 1.5358x; 1.0068x over previous
#include <cuda_runtime.h>
#include <cstdint>
#include <math.h>

// ----------------------------------------------------------------------------
// DLRM forward. R12->R13:
//  (a) GEMM: hi/lo TF32 split done ONCE at smem-store (truncation split:
//      hi = bits&0xFFFFE000, lo = x-hi exact; lo masked too), stored packed
//      uint2 -> fragment loads are single LDS.64. XOR-rotation swizzle
//      (c + 4*(row&3))&15 keeps .64 accesses conflict-free, no padding.
//      Inner-loop issue count ~200 -> ~128 per thread per k-iter.
//  (b) interact: 2x2 pair tiling (91 tiles) halves LDS traffic.
// ----------------------------------------------------------------------------

#define BB      8192
#define NTAB    26
#define LBAG    10
#define VROWS   200000
#define DD      64
#define TROW    1728        // 27*64 floats per batch row of T
#define RLD     416         // padded row stride of R (415 used)
#define NEMB    (NTAB * (BB / 16))   // 13312 embed blocks (16 bags each)

// ---------------- scratch (device globals: no allocs allowed) ----------------
__device__ __align__(16) float g_h1[BB * 512];
__device__ __align__(16) float g_h2[BB * 256];
__device__ __align__(16) float g_T [BB * TROW];
__device__ __align__(16) float g_R [BB * RLD];
__device__ int g_idx64;

// ---------------- helpers ----------------
__device__ __forceinline__ void mma_tf32(float* d, const uint32_t* a, const uint32_t* b) {
    asm volatile(
        "mma.sync.aligned.m16n8k8.row.col.f32.tf32.tf32.f32 "
        "{%0,%1,%2,%3}, {%4,%5,%6,%7}, {%8,%9}, {%0,%1,%2,%3};\n"
        : "+f"(d[0]), "+f"(d[1]), "+f"(d[2]), "+f"(d[3])
        : "r"(a[0]), "r"(a[1]), "r"(a[2]), "r"(a[3]), "r"(b[0]), "r"(b[1]));
}

// truncation-based tf32 split: hi = top bits (exact tf32), lo = x - hi (exact
// fp32 by Sterbenz), then lo masked to tf32 bits. |err| per product ~2^-20.
__device__ __forceinline__ uint2 split_tf32(float x) {
    const uint32_t hb = __float_as_uint(x) & 0xFFFFE000u;
    const float lo = x - __uint_as_float(hb);
    return make_uint2(hb, __float_as_uint(lo) & 0xFFFFE000u);
}

// per-row column rotation: conflict-free LDS.64 / STS.64 (see theory)
__device__ __forceinline__ int swz(int c, int r) { return (c + 4 * (r & 3)) & 15; }

// ---------------- index-width autodetect ----------------
__global__ void detect_idx_kernel(const unsigned int* __restrict__ p) {
    if (threadIdx.x == 0 && blockIdx.x == 0) {
        int f = 1;
        for (int i = 0; i < 128; i++) {
            if (p[2 * i + 1] != 0u) { f = 0; break; }
        }
        g_idx64 = f;
    }
}

// ---------------- embedding bag block (device side) -------------------------
__device__ __forceinline__ void embed_block(int e, const void* __restrict__ lSi,
                                            const float* __restrict__ emb)
{
    const int c   = threadIdx.x & 15;
    const int bag = threadIdx.x >> 4;
    const int t   = e >> 9;
    const int b   = ((e & 511) << 4) + bag;

    const float4* tab = reinterpret_cast<const float4*>(emb)
                      + (size_t)t * (size_t)(VROWS * (DD / 4));
    const long long ibase = (long long)t * (BB * LBAG) + (long long)b * LBAG;

    int idx[LBAG];
    if (g_idx64) {
        const long long* I = reinterpret_cast<const long long*>(lSi);
        #pragma unroll
        for (int j = 0; j < LBAG; j++) idx[j] = (int)I[ibase + j];
    } else {
        const int* I = reinterpret_cast<const int*>(lSi);
        #pragma unroll
        for (int j = 0; j < LBAG; j++) idx[j] = I[ibase + j];
    }

    float4 acc = make_float4(0.f, 0.f, 0.f, 0.f);
    #pragma unroll
    for (int j = 0; j < LBAG; j++) {
        const float4 v = __ldg(&tab[(size_t)idx[j] * (DD / 4) + c]);
        acc.x += v.x; acc.y += v.y; acc.z += v.z; acc.w += v.w;
    }
    reinterpret_cast<float4*>(g_T)[(size_t)b * (TROW / 4) + (1 + t) * (DD / 4) + c] = acc;
}

// ---------------- fused GEMM (+ optional embed blocks) ----------------------
// C = relu(A[8192,K] @ W[M,K]^T + bias). Block tile 128x64, BK=16, 256 thr =
// 8 warps (4m x 2n), warp tile 32x32. Double-buffered smem of PACKED (hi,lo)
// uint2; one sync per k-iter; LDS.64 fragment loads.
__global__ __launch_bounds__(256)
void fused_gemm_embed(const float* __restrict__ A, int lda,
                      const float* __restrict__ W, int K,
                      const float* __restrict__ bias,
                      float* __restrict__ C, int ldc,
                      int gridGx, int nGemm,
                      const void* __restrict__ lSi,
                      const float* __restrict__ emb,
                      int embBase)
{
    if ((int)blockIdx.x >= nGemm) {
        embed_block((int)blockIdx.x - nGemm + embBase, lSi, emb);
        return;
    }

    __shared__ uint2 As[2][128][16];   // packed (hi,lo), swizzled cols
    __shared__ uint2 Ws[2][64][16];    // total static smem = 48 KB exactly

    const int tid  = threadIdx.x;
    const int kld  = tid & 15;
    const int mth  = tid >> 4;
    const int warp = tid >> 5;
    const int lane = tid & 31;
    const int wm   = warp & 3;
    const int wn   = warp >> 2;
    const int gid  = lane >> 2;
    const int tig  = lane & 3;

    // store-side swizzled column (row&3 == mth&3 for all rows mth+16i)
    const int scol = swz(kld, mth);
    // fragment-side swizzled columns (row&3 == gid&3 for all fragment rows)
    const int fc0 = swz(tig,      gid);
    const int fc1 = swz(tig + 4,  gid);
    const int fc2 = swz(tig + 8,  gid);
    const int fc3 = swz(tig + 12, gid);

    const int bx = (int)blockIdx.x % gridGx;
    const int by = (int)blockIdx.x / gridGx;
    const long long rowBase = (long long)by * 128;
    const int colBase = bx * 64;

    float acc[2][4][4];
    #pragma unroll
    for (int mt = 0; mt < 2; mt++)
        #pragma unroll
        for (int nt = 0; nt < 4; nt++)
            #pragma unroll
            for (int q = 0; q < 4; q++) acc[mt][nt][q] = 0.0f;

    float aR[8], wR[4];

    // ---- prologue: load k-tile 0 -> regs -> split -> smem stage 0 ----
    {
        const int gk = kld;
        const bool kin = (gk < K);
        #pragma unroll
        for (int i = 0; i < 8; i++) {
            const int m = mth + 16 * i;
            aR[i] = kin ? __ldg(&A[(rowBase + m) * (long long)lda + gk]) : 0.0f;
        }
        #pragma unroll
        for (int i = 0; i < 4; i++) {
            const int n = mth + 16 * i;
            wR[i] = kin ? __ldg(&W[(size_t)(colBase + n) * (size_t)K + gk]) : 0.0f;
        }
        #pragma unroll
        for (int i = 0; i < 8; i++) As[0][mth + 16 * i][scol] = split_tf32(aR[i]);
        #pragma unroll
        for (int i = 0; i < 4; i++) Ws[0][mth + 16 * i][scol] = split_tf32(wR[i]);
    }
    __syncthreads();

    int s = 0;
    for (int k0 = 0; k0 < K; k0 += 16) {
        const bool more = (k0 + 16) < K;

        // ---- prefetch next k-tile into registers (overlaps MMAs below) ----
        if (more) {
            const int gk = k0 + 16 + kld;
            const bool kin = (gk < K);
            #pragma unroll
            for (int i = 0; i < 8; i++) {
                const int m = mth + 16 * i;
                aR[i] = kin ? __ldg(&A[(rowBase + m) * (long long)lda + gk]) : 0.0f;
            }
            #pragma unroll
            for (int i = 0; i < 4; i++) {
                const int n = mth + 16 * i;
                wR[i] = kin ? __ldg(&W[(size_t)(colBase + n) * (size_t)K + gk]) : 0.0f;
            }
        }

        // ---- MMA section on stage s (packed fragments, LDS.64) ----
        #pragma unroll
        for (int kk = 0; kk < 2; kk++) {
            const int c0 = kk ? fc2 : fc0;     // k = kk*8 + tig
            const int c1 = kk ? fc3 : fc1;     // k = kk*8 + tig + 4
            uint32_t a_hi[2][4], a_lo[2][4];
            #pragma unroll
            for (int mt = 0; mt < 2; mt++) {
                const int r = wm * 32 + mt * 16 + gid;
                const uint2 p0 = As[s][r    ][c0];
                const uint2 p1 = As[s][r + 8][c0];
                const uint2 p2 = As[s][r    ][c1];
                const uint2 p3 = As[s][r + 8][c1];
                a_hi[mt][0] = p0.x; a_lo[mt][0] = p0.y;
                a_hi[mt][1] = p1.x; a_lo[mt][1] = p1.y;
                a_hi[mt][2] = p2.x; a_lo[mt][2] = p2.y;
                a_hi[mt][3] = p3.x; a_lo[mt][3] = p3.y;
            }
            uint32_t b_hi[4][2], b_lo[4][2];
            #pragma unroll
            for (int nt = 0; nt < 4; nt++) {
                const int n = wn * 32 + nt * 8 + gid;
                const uint2 q0 = Ws[s][n][c0];
                const uint2 q1 = Ws[s][n][c1];
                b_hi[nt][0] = q0.x; b_lo[nt][0] = q0.y;
                b_hi[nt][1] = q1.x; b_lo[nt][1] = q1.y;
            }
            #pragma unroll
            for (int mt = 0; mt < 2; mt++)
                #pragma unroll
                for (int nt = 0; nt < 4; nt++) {
                    mma_tf32(acc[mt][nt], a_hi[mt], b_hi[nt]);
                    mma_tf32(acc[mt][nt], a_hi[mt], b_lo[nt]);
                    mma_tf32(acc[mt][nt], a_lo[mt], b_hi[nt]);
                }
        }

        // ---- split + store prefetched tile into the other stage ----
        if (more) {
            #pragma unroll
            for (int i = 0; i < 8; i++) As[s ^ 1][mth + 16 * i][scol] = split_tf32(aR[i]);
            #pragma unroll
            for (int i = 0; i < 4; i++) Ws[s ^ 1][mth + 16 * i][scol] = split_tf32(wR[i]);
        }
        __syncthreads();
        s ^= 1;
    }

    // ---- epilogue: bias + relu, float2 stores ----
    #pragma unroll
    for (int mt = 0; mt < 2; mt++)
        #pragma unroll
        for (int nt = 0; nt < 4; nt++) {
            const long long row = rowBase + wm * 32 + mt * 16 + gid;
            const int col = colBase + wn * 32 + nt * 8 + 2 * tig;
            const float b0 = bias[col];
            const float b1 = bias[col + 1];
            float2 v01, v23;
            v01.x = fmaxf(acc[mt][nt][0] + b0, 0.0f);
            v01.y = fmaxf(acc[mt][nt][1] + b1, 0.0f);
            v23.x = fmaxf(acc[mt][nt][2] + b0, 0.0f);
            v23.y = fmaxf(acc[mt][nt][3] + b1, 0.0f);
            *reinterpret_cast<float2*>(&C[row * ldc + col])       = v01;
            *reinterpret_cast<float2*>(&C[(row + 8) * ldc + col]) = v23;
        }
}

// ---------------- dot interaction: R[b] = [h(64), tril dots(351)] -----------
// 2x2 pair tiling: 91 tiles (78 full, 13 diagonal w/ 3 valid pairs). Each
// thread loads 4 rows for 4 dots -> half the LDS traffic of pair-per-thread.
// Smem rows padded to 17 float4 (conflict-free / broadcast).
__global__ void interact_kernel()
{
    __shared__ __align__(16) float Ts[27 * 68];
    const int b = blockIdx.x;
    const float4* Tb = reinterpret_cast<const float4*>(g_T + (size_t)b * TROW);
    float4* Ts4 = reinterpret_cast<float4*>(Ts);

    for (int g = threadIdx.x; g < TROW / 4; g += 128) {
        const int r = g >> 4;
        const int c = g & 15;
        Ts4[r * 17 + c] = Tb[g];
    }
    __syncthreads();

    float* Rb = g_R + (size_t)b * RLD;
    if (threadIdx.x < 64) Rb[threadIdx.x] = Ts[threadIdx.x];   // row 0 = h

    for (int t = threadIdx.x; t < 91; t += 128) {
        // invert t -> (ti, tj): t = ti*(ti+1)/2 + tj, tj <= ti  (13x13 tril+diag)
        int ti = (int)((sqrtf(8.0f * (float)t + 1.0f) - 1.0f) * 0.5f);
        while (ti * (ti + 1) / 2 > t) --ti;
        while ((ti + 1) * (ti + 2) / 2 <= t) ++ti;
        const int tj = t - ti * (ti + 1) / 2;
        const int i0 = 2 * ti + 1;     // rows i0, i0+1  (1..26)
        const int j0 = 2 * tj;         // rows j0, j0+1  (0..25)

        const float4* u0 = Ts4 + i0 * 17;
        const float4* u1 = u0 + 17;
        const float4* v0 = Ts4 + j0 * 17;
        const float4* v1 = v0 + 17;
        float s00 = 0.f, s01 = 0.f, s10 = 0.f, s11 = 0.f;
        #pragma unroll
        for (int k = 0; k < DD / 4; k++) {
            const float4 a0 = u0[k], a1 = u1[k], c0 = v0[k], c1 = v1[k];
            s00 += a0.x * c0.x + a0.y * c0.y + a0.z * c0.z + a0.w * c0.w;
            s01 += a0.x * c1.x + a0.y * c1.y + a0.z * c1.z + a0.w * c1.w;
            s10 += a1.x * c0.x + a1.y * c0.y + a1.z * c0.z + a1.w * c0.w;
            s11 += a1.x * c1.x + a1.y * c1.y + a1.z * c1.z + a1.w * c1.w;
        }
        const int bi0 = i0 * (i0 - 1) / 2;         // tril base for row i0
        const int bi1 = i0 * (i0 + 1) / 2;         // tril base for row i0+1
        Rb[64 + bi0 + j0] = s00;
        if (ti != tj) Rb[64 + bi0 + j0 + 1] = s01; // skip j==i on diagonal tiles
        Rb[64 + bi1 + j0]     = s10;
        Rb[64 + bi1 + j0 + 1] = s11;
    }
}

// ---------------- top layer 3: out[b] = sigmoid(dot(z2[b], w3) + b3) --------
__global__ void top3_kernel(const float* __restrict__ w3, const float* __restrict__ b3,
                            float* __restrict__ out)
{
    const int gwarp = (int)((blockIdx.x * blockDim.x + threadIdx.x) >> 5);
    const int lane  = threadIdx.x & 31;
    const float4* z = reinterpret_cast<const float4*>(g_h2) + (size_t)gwarp * 64;
    const float4* w = reinterpret_cast<const float4*>(w3);

    const float4 z0 = z[lane],      w0 = w[lane];
    const float4 z1 = z[lane + 32], w1 = w[lane + 32];
    float s = z0.x * w0.x + z0.y * w0.y + z0.z * w0.z + z0.w * w0.w
            + z1.x * w1.x + z1.y * w1.y + z1.z * w1.z + z1.w * w1.w;
    #pragma unroll
    for (int o = 16; o > 0; o >>= 1) s += __shfl_xor_sync(0xffffffffu, s, o);
    if (lane == 0) out[gwarp] = 1.0f / (1.0f + expf(-(s + b3[0])));
}

// ---------------- host ----------------
static void run_fused(const float* A, int lda, const float* W, int K,
                      const float* bias, float* C, int ldc, int M,
                      const void* lSi, const float* emb, int embBase, int embCount)
{
    const int gridGx = M / 64;
    const int nGemm  = gridGx * (BB / 128);
    fused_gemm_embed<<<nGemm + embCount, 256>>>(A, lda, W, K, bias, C, ldc,
                                                gridGx, nGemm, lSi, emb, embBase);
}

extern "C" void kernel_launch(void* const* d_in, const int* in_sizes, int n_in,
                              void* d_out, int out_size)
{
    int IX_X, IX_LSI, IX_EMB, IX_BW1, IX_BB1, IX_BW2, IX_BB2, IX_BW3, IX_BB3;
    int IX_TW1, IX_TB1, IX_TW2, IX_TB2, IX_TW3, IX_TB3;
    if (in_sizes[0] == BB * 13) {
        IX_X = 0; IX_LSI = 1; IX_EMB = 3;
        IX_BW1 = 4;  IX_BB1 = 5;  IX_BW2 = 6;  IX_BB2 = 7;  IX_BW3 = 8;  IX_BB3 = 9;
        IX_TW1 = 10; IX_TB1 = 11; IX_TW2 = 12; IX_TB2 = 13; IX_TW3 = 14; IX_TB3 = 15;
    } else {
        IX_BW1 = 0; IX_BW2 = 1; IX_BW3 = 2; IX_BB1 = 3; IX_BB2 = 4; IX_BB3 = 5;
        IX_EMB = 6; IX_LSI = 7;
        IX_TW1 = 9; IX_TW2 = 10; IX_TW3 = 11; IX_TB1 = 12; IX_TB2 = 13; IX_TB3 = 14;
        IX_X = 15;
    }

    const float* x    = (const float*)d_in[IX_X];
    const void*  lSi  = d_in[IX_LSI];
    const float* emb  = (const float*)d_in[IX_EMB];
    const float* bw1  = (const float*)d_in[IX_BW1];
    const float* bb1  = (const float*)d_in[IX_BB1];
    const float* bw2  = (const float*)d_in[IX_BW2];
    const float* bb2  = (const float*)d_in[IX_BB2];
    const float* bw3  = (const float*)d_in[IX_BW3];
    const float* bb3  = (const float*)d_in[IX_BB3];
    const float* tw1  = (const float*)d_in[IX_TW1];
    const float* tb1  = (const float*)d_in[IX_TB1];
    const float* tw2  = (const float*)d_in[IX_TW2];
    const float* tb2  = (const float*)d_in[IX_TB2];
    const float* tw3  = (const float*)d_in[IX_TW3];
    const float* tb3  = (const float*)d_in[IX_TB3];
    float* out = (float*)d_out;

    float *h1, *h2, *T, *R;
    cudaGetSymbolAddress((void**)&h1, g_h1);
    cudaGetSymbolAddress((void**)&h2, g_h2);
    cudaGetSymbolAddress((void**)&T,  g_T);
    cudaGetSymbolAddress((void**)&R,  g_R);

    detect_idx_kernel<<<1, 32>>>((const unsigned int*)lSi);

    // bottom MLP fused with embedding-bag blocks
    const int E1 = 4438, E2 = 4437, E3 = NEMB - 4438 - 4437;
    run_fused(x,  13,  bw1, 13,  bb1, h1, 512, 512, lSi, emb, 0,       E1);
    run_fused(h1, 512, bw2, 512, bb2, h2, 256, 256, lSi, emb, E1,      E2);
    run_fused(h2, 256, bw3, 256, bb3, T,  TROW, 64, lSi, emb, E1 + E2, E3);

    // dot interaction
    interact_kernel<<<BB, 128>>>();

    // top MLP
    run_fused(R,  RLD, tw1, 415, tb1, h1, 512, 512, lSi, emb, 0, 0);
    run_fused(h1, 512, tw2, 512, tb2, h2, 256, 256, lSi, emb, 0, 0);

    // final 256 -> 1 dot + sigmoid
    top3_kernel<<<BB / 8, 256>>>(tw3, tb3, out);
}

// round 15
// speedup vs baseline: 1.7619x; 1.1472x over previous
#include <cuda_runtime.h>
#include <cuda_bf16.h>
#include <cstdint>
#include <math.h>

// ----------------------------------------------------------------------------
// DLRM forward. R13->R14: GEMM math switched from 3xTF32 (m16n8k8 pairs) to
// 3-term bf16 split (m16n8k16): hi = rn_bf16(x), lo = rn_bf16(x - hi);
// D += ah*bh + ah*bl + al*bh. Halves MMA instruction count and smem bytes.
// Smem holds bf16 "planes" (hi and lo), k-pairs packed in uint32, row stride
// 9 words (near-conflict-free). Accumulator layout identical to k8 -> epilogue
// and double-buffer skeleton unchanged. Embed/interact/top3 unchanged.
// ----------------------------------------------------------------------------

#define BB      8192
#define NTAB    26
#define LBAG    10
#define VROWS   200000
#define DD      64
#define TROW    1728        // 27*64 floats per batch row of T
#define RLD     416         // padded row stride of R (415 used)
#define NEMB    (NTAB * (BB / 16))   // 13312 embed blocks (16 bags each)

// ---------------- scratch (device globals: no allocs allowed) ----------------
__device__ __align__(16) float g_h1[BB * 512];
__device__ __align__(16) float g_h2[BB * 256];
__device__ __align__(16) float g_T [BB * TROW];
__device__ __align__(16) float g_R [BB * RLD];
__device__ int g_idx64;

// ---------------- helpers ----------------
__device__ __forceinline__ void mma_bf16(float* d, const uint32_t* a, const uint32_t* b) {
    asm volatile(
        "mma.sync.aligned.m16n8k16.row.col.f32.bf16.bf16.f32 "
        "{%0,%1,%2,%3}, {%4,%5,%6,%7}, {%8,%9}, {%0,%1,%2,%3};\n"
        : "+f"(d[0]), "+f"(d[1]), "+f"(d[2]), "+f"(d[3])
        : "r"(a[0]), "r"(a[1]), "r"(a[2]), "r"(a[3]), "r"(b[0]), "r"(b[1]));
}

// split one k-pair (v0 = even k, v1 = odd k) into packed bf16 hi/lo words.
// hi word: low half = bf16(v0), high half = bf16(v1). lo plane likewise.
__device__ __forceinline__ void split_pair(float v0, float v1,
                                           uint32_t& hiw, uint32_t& low)
{
    const __nv_bfloat16 h0 = __float2bfloat16_rn(v0);
    const __nv_bfloat16 h1 = __float2bfloat16_rn(v1);
    const float r0 = v0 - __bfloat162float(h0);
    const float r1 = v1 - __bfloat162float(h1);
    const __nv_bfloat162 hp = __nv_bfloat162(h0, h1);
    const __nv_bfloat162 lp = __floats2bfloat162_rn(r0, r1);
    hiw = *reinterpret_cast<const uint32_t*>(&hp);
    low = *reinterpret_cast<const uint32_t*>(&lp);
}

// ---------------- index-width autodetect ----------------
__global__ void detect_idx_kernel(const unsigned int* __restrict__ p) {
    if (threadIdx.x == 0 && blockIdx.x == 0) {
        int f = 1;
        for (int i = 0; i < 128; i++) {
            if (p[2 * i + 1] != 0u) { f = 0; break; }
        }
        g_idx64 = f;
    }
}

// ---------------- embedding bag block (device side) -------------------------
__device__ __forceinline__ void embed_block(int e, const void* __restrict__ lSi,
                                            const float* __restrict__ emb)
{
    const int c   = threadIdx.x & 15;
    const int bag = threadIdx.x >> 4;
    const int t   = e >> 9;
    const int b   = ((e & 511) << 4) + bag;

    const float4* tab = reinterpret_cast<const float4*>(emb)
                      + (size_t)t * (size_t)(VROWS * (DD / 4));
    const long long ibase = (long long)t * (BB * LBAG) + (long long)b * LBAG;

    int idx[LBAG];
    if (g_idx64) {
        const long long* I = reinterpret_cast<const long long*>(lSi);
        #pragma unroll
        for (int j = 0; j < LBAG; j++) idx[j] = (int)I[ibase + j];
    } else {
        const int* I = reinterpret_cast<const int*>(lSi);
        #pragma unroll
        for (int j = 0; j < LBAG; j++) idx[j] = I[ibase + j];
    }

    float4 acc = make_float4(0.f, 0.f, 0.f, 0.f);
    #pragma unroll
    for (int j = 0; j < LBAG; j++) {
        const float4 v = __ldg(&tab[(size_t)idx[j] * (DD / 4) + c]);
        acc.x += v.x; acc.y += v.y; acc.z += v.z; acc.w += v.w;
    }
    reinterpret_cast<float4*>(g_T)[(size_t)b * (TROW / 4) + (1 + t) * (DD / 4) + c] = acc;
}

// ---------------- fused GEMM (+ optional embed blocks) ----------------------
// C = relu(A[8192,K] @ W[M,K]^T + bias). Block tile 128x64, BK=16, 256 thr =
// 8 warps (4m x 2n), warp tile 32x32. bf16 3-term, m16n8k16. Double-buffered
// hi/lo bf16 planes; one sync per k-iter; register-prefetch pipeline.
__global__ __launch_bounds__(256)
void fused_gemm_embed(const float* __restrict__ A, int lda,
                      const float* __restrict__ W, int K,
                      const float* __restrict__ bias,
                      float* __restrict__ C, int ldc,
                      int gridGx, int nGemm,
                      const void* __restrict__ lSi,
                      const float* __restrict__ emb,
                      int embBase)
{
    if ((int)blockIdx.x >= nGemm) {
        embed_block((int)blockIdx.x - nGemm + embBase, lSi, emb);
        return;
    }

    // bf16 planes, k-pairs (8 per BK=16) packed in uint32, row stride 9 words
    __shared__ uint32_t Ah[2][128 * 9];
    __shared__ uint32_t Al[2][128 * 9];
    __shared__ uint32_t Wh[2][64 * 9];
    __shared__ uint32_t Wl[2][64 * 9];

    const int tid  = threadIdx.x;
    const int kp   = tid & 7;         // k-pair this thread loads (k = 2kp, 2kp+1)
    const int rth  = tid >> 3;        // 0..31: base row this thread loads
    const int warp = tid >> 5;
    const int lane = tid & 31;
    const int wm   = warp & 3;
    const int wn   = warp >> 2;
    const int gid  = lane >> 2;
    const int tig  = lane & 3;

    const int bx = (int)blockIdx.x % gridGx;
    const int by = (int)blockIdx.x / gridGx;
    const long long rowBase = (long long)by * 128;
    const int colBase = bx * 64;

    float acc[2][4][4];
    #pragma unroll
    for (int mt = 0; mt < 2; mt++)
        #pragma unroll
        for (int nt = 0; nt < 4; nt++)
            #pragma unroll
            for (int q = 0; q < 4; q++) acc[mt][nt][q] = 0.0f;

    float a0R[4], a1R[4], w0R[2], w1R[2];

    // ---- prologue: load k-tile 0 -> regs -> split -> smem stage 0 ----
    {
        const int g0 = 2 * kp, g1 = 2 * kp + 1;
        const bool in0 = (g0 < K), in1 = (g1 < K);
        #pragma unroll
        for (int i = 0; i < 4; i++) {
            const long long m = rowBase + rth + 32 * i;
            a0R[i] = in0 ? __ldg(&A[m * lda + g0]) : 0.0f;
            a1R[i] = in1 ? __ldg(&A[m * lda + g1]) : 0.0f;
        }
        #pragma unroll
        for (int i = 0; i < 2; i++) {
            const size_t n = (size_t)(colBase + rth + 32 * i);
            w0R[i] = in0 ? __ldg(&W[n * (size_t)K + g0]) : 0.0f;
            w1R[i] = in1 ? __ldg(&W[n * (size_t)K + g1]) : 0.0f;
        }
        #pragma unroll
        for (int i = 0; i < 4; i++) {
            uint32_t h, l; split_pair(a0R[i], a1R[i], h, l);
            Ah[0][(rth + 32 * i) * 9 + kp] = h;
            Al[0][(rth + 32 * i) * 9 + kp] = l;
        }
        #pragma unroll
        for (int i = 0; i < 2; i++) {
            uint32_t h, l; split_pair(w0R[i], w1R[i], h, l);
            Wh[0][(rth + 32 * i) * 9 + kp] = h;
            Wl[0][(rth + 32 * i) * 9 + kp] = l;
        }
    }
    __syncthreads();

    int s = 0;
    for (int k0 = 0; k0 < K; k0 += 16) {
        const bool more = (k0 + 16) < K;

        // ---- prefetch next k-tile into registers (overlaps MMAs below) ----
        if (more) {
            const int g0 = k0 + 16 + 2 * kp, g1 = g0 + 1;
            const bool in0 = (g0 < K), in1 = (g1 < K);
            #pragma unroll
            for (int i = 0; i < 4; i++) {
                const long long m = rowBase + rth + 32 * i;
                a0R[i] = in0 ? __ldg(&A[m * lda + g0]) : 0.0f;
                a1R[i] = in1 ? __ldg(&A[m * lda + g1]) : 0.0f;
            }
            #pragma unroll
            for (int i = 0; i < 2; i++) {
                const size_t n = (size_t)(colBase + rth + 32 * i);
                w0R[i] = in0 ? __ldg(&W[n * (size_t)K + g0]) : 0.0f;
                w1R[i] = in1 ? __ldg(&W[n * (size_t)K + g1]) : 0.0f;
            }
        }

        // ---- MMA section on stage s (one m16n8k16 chunk per iter) ----
        {
            uint32_t a_hi[2][4], a_lo[2][4];
            #pragma unroll
            for (int mt = 0; mt < 2; mt++) {
                const int r = wm * 32 + mt * 16 + gid;
                a_hi[mt][0] = Ah[s][r * 9 + tig];
                a_hi[mt][1] = Ah[s][(r + 8) * 9 + tig];
                a_hi[mt][2] = Ah[s][r * 9 + tig + 4];
                a_hi[mt][3] = Ah[s][(r + 8) * 9 + tig + 4];
                a_lo[mt][0] = Al[s][r * 9 + tig];
                a_lo[mt][1] = Al[s][(r + 8) * 9 + tig];
                a_lo[mt][2] = Al[s][r * 9 + tig + 4];
                a_lo[mt][3] = Al[s][(r + 8) * 9 + tig + 4];
            }
            uint32_t b_hi[4][2], b_lo[4][2];
            #pragma unroll
            for (int nt = 0; nt < 4; nt++) {
                const int n = wn * 32 + nt * 8 + gid;
                b_hi[nt][0] = Wh[s][n * 9 + tig];
                b_hi[nt][1] = Wh[s][n * 9 + tig + 4];
                b_lo[nt][0] = Wl[s][n * 9 + tig];
                b_lo[nt][1] = Wl[s][n * 9 + tig + 4];
            }
            #pragma unroll
            for (int mt = 0; mt < 2; mt++)
                #pragma unroll
                for (int nt = 0; nt < 4; nt++) {
                    mma_bf16(acc[mt][nt], a_hi[mt], b_hi[nt]);
                    mma_bf16(acc[mt][nt], a_hi[mt], b_lo[nt]);
                    mma_bf16(acc[mt][nt], a_lo[mt], b_hi[nt]);
                }
        }

        // ---- split + store prefetched tile into the other stage ----
        if (more) {
            #pragma unroll
            for (int i = 0; i < 4; i++) {
                uint32_t h, l; split_pair(a0R[i], a1R[i], h, l);
                Ah[s ^ 1][(rth + 32 * i) * 9 + kp] = h;
                Al[s ^ 1][(rth + 32 * i) * 9 + kp] = l;
            }
            #pragma unroll
            for (int i = 0; i < 2; i++) {
                uint32_t h, l; split_pair(w0R[i], w1R[i], h, l);
                Wh[s ^ 1][(rth + 32 * i) * 9 + kp] = h;
                Wl[s ^ 1][(rth + 32 * i) * 9 + kp] = l;
            }
        }
        __syncthreads();
        s ^= 1;
    }

    // ---- epilogue: bias + relu, float2 stores (same acc layout as k8) ----
    #pragma unroll
    for (int mt = 0; mt < 2; mt++)
        #pragma unroll
        for (int nt = 0; nt < 4; nt++) {
            const long long row = rowBase + wm * 32 + mt * 16 + gid;
            const int col = colBase + wn * 32 + nt * 8 + 2 * tig;
            const float b0 = bias[col];
            const float b1 = bias[col + 1];
            float2 v01, v23;
            v01.x = fmaxf(acc[mt][nt][0] + b0, 0.0f);
            v01.y = fmaxf(acc[mt][nt][1] + b1, 0.0f);
            v23.x = fmaxf(acc[mt][nt][2] + b0, 0.0f);
            v23.y = fmaxf(acc[mt][nt][3] + b1, 0.0f);
            *reinterpret_cast<float2*>(&C[row * ldc + col])       = v01;
            *reinterpret_cast<float2*>(&C[(row + 8) * ldc + col]) = v23;
        }
}

// ---------------- dot interaction: R[b] = [h(64), tril dots(351)] -----------
// 2x2 pair tiling: 91 tiles (78 full, 13 diagonal w/ 3 valid pairs).
__global__ void interact_kernel()
{
    __shared__ __align__(16) float Ts[27 * 68];
    const int b = blockIdx.x;
    const float4* Tb = reinterpret_cast<const float4*>(g_T + (size_t)b * TROW);
    float4* Ts4 = reinterpret_cast<float4*>(Ts);

    for (int g = threadIdx.x; g < TROW / 4; g += 128) {
        const int r = g >> 4;
        const int c = g & 15;
        Ts4[r * 17 + c] = Tb[g];
    }
    __syncthreads();

    float* Rb = g_R + (size_t)b * RLD;
    if (threadIdx.x < 64) Rb[threadIdx.x] = Ts[threadIdx.x];   // row 0 = h

    for (int t = threadIdx.x; t < 91; t += 128) {
        int ti = (int)((sqrtf(8.0f * (float)t + 1.0f) - 1.0f) * 0.5f);
        while (ti * (ti + 1) / 2 > t) --ti;
        while ((ti + 1) * (ti + 2) / 2 <= t) ++ti;
        const int tj = t - ti * (ti + 1) / 2;
        const int i0 = 2 * ti + 1;
        const int j0 = 2 * tj;

        const float4* u0 = Ts4 + i0 * 17;
        const float4* u1 = u0 + 17;
        const float4* v0 = Ts4 + j0 * 17;
        const float4* v1 = v0 + 17;
        float s00 = 0.f, s01 = 0.f, s10 = 0.f, s11 = 0.f;
        #pragma unroll
        for (int k = 0; k < DD / 4; k++) {
            const float4 a0 = u0[k], a1 = u1[k], c0 = v0[k], c1 = v1[k];
            s00 += a0.x * c0.x + a0.y * c0.y + a0.z * c0.z + a0.w * c0.w;
            s01 += a0.x * c1.x + a0.y * c1.y + a0.z * c1.z + a0.w * c1.w;
            s10 += a1.x * c0.x + a1.y * c0.y + a1.z * c0.z + a1.w * c0.w;
            s11 += a1.x * c1.x + a1.y * c1.y + a1.z * c1.z + a1.w * c1.w;
        }
        const int bi0 = i0 * (i0 - 1) / 2;
        const int bi1 = i0 * (i0 + 1) / 2;
        Rb[64 + bi0 + j0] = s00;
        if (ti != tj) Rb[64 + bi0 + j0 + 1] = s01;
        Rb[64 + bi1 + j0]     = s10;
        Rb[64 + bi1 + j0 + 1] = s11;
    }
}

// ---------------- top layer 3: out[b] = sigmoid(dot(z2[b], w3) + b3) --------
__global__ void top3_kernel(const float* __restrict__ w3, const float* __restrict__ b3,
                            float* __restrict__ out)
{
    const int gwarp = (int)((blockIdx.x * blockDim.x + threadIdx.x) >> 5);
    const int lane  = threadIdx.x & 31;
    const float4* z = reinterpret_cast<const float4*>(g_h2) + (size_t)gwarp * 64;
    const float4* w = reinterpret_cast<const float4*>(w3);

    const float4 z0 = z[lane],      w0 = w[lane];
    const float4 z1 = z[lane + 32], w1 = w[lane + 32];
    float s = z0.x * w0.x + z0.y * w0.y + z0.z * w0.z + z0.w * w0.w
            + z1.x * w1.x + z1.y * w1.y + z1.z * w1.z + z1.w * w1.w;
    #pragma unroll
    for (int o = 16; o > 0; o >>= 1) s += __shfl_xor_sync(0xffffffffu, s, o);
    if (lane == 0) out[gwarp] = 1.0f / (1.0f + expf(-(s + b3[0])));
}

// ---------------- host ----------------
static void run_fused(const float* A, int lda, const float* W, int K,
                      const float* bias, float* C, int ldc, int M,
                      const void* lSi, const float* emb, int embBase, int embCount)
{
    const int gridGx = M / 64;
    const int nGemm  = gridGx * (BB / 128);
    fused_gemm_embed<<<nGemm + embCount, 256>>>(A, lda, W, K, bias, C, ldc,
                                                gridGx, nGemm, lSi, emb, embBase);
}

extern "C" void kernel_launch(void* const* d_in, const int* in_sizes, int n_in,
                              void* d_out, int out_size)
{
    int IX_X, IX_LSI, IX_EMB, IX_BW1, IX_BB1, IX_BW2, IX_BB2, IX_BW3, IX_BB3;
    int IX_TW1, IX_TB1, IX_TW2, IX_TB2, IX_TW3, IX_TB3;
    if (in_sizes[0] == BB * 13) {
        IX_X = 0; IX_LSI = 1; IX_EMB = 3;
        IX_BW1 = 4;  IX_BB1 = 5;  IX_BW2 = 6;  IX_BB2 = 7;  IX_BW3 = 8;  IX_BB3 = 9;
        IX_TW1 = 10; IX_TB1 = 11; IX_TW2 = 12; IX_TB2 = 13; IX_TW3 = 14; IX_TB3 = 15;
    } else {
        IX_BW1 = 0; IX_BW2 = 1; IX_BW3 = 2; IX_BB1 = 3; IX_BB2 = 4; IX_BB3 = 5;
        IX_EMB = 6; IX_LSI = 7;
        IX_TW1 = 9; IX_TW2 = 10; IX_TW3 = 11; IX_TB1 = 12; IX_TB2 = 13; IX_TB3 = 14;
        IX_X = 15;
    }

    const float* x    = (const float*)d_in[IX_X];
    const void*  lSi  = d_in[IX_LSI];
    const float* emb  = (const float*)d_in[IX_EMB];
    const float* bw1  = (const float*)d_in[IX_BW1];
    const float* bb1  = (const float*)d_in[IX_BB1];
    const float* bw2  = (const float*)d_in[IX_BW2];
    const float* bb2  = (const float*)d_in[IX_BB2];
    const float* bw3  = (const float*)d_in[IX_BW3];
    const float* bb3  = (const float*)d_in[IX_BB3];
    const float* tw1  = (const float*)d_in[IX_TW1];
    const float* tb1  = (const float*)d_in[IX_TB1];
    const float* tw2  = (const float*)d_in[IX_TW2];
    const float* tb2  = (const float*)d_in[IX_TB2];
    const float* tw3  = (const float*)d_in[IX_TW3];
    const float* tb3  = (const float*)d_in[IX_TB3];
    float* out = (float*)d_out;

    float *h1, *h2, *T, *R;
    cudaGetSymbolAddress((void**)&h1, g_h1);
    cudaGetSymbolAddress((void**)&h2, g_h2);
    cudaGetSymbolAddress((void**)&T,  g_T);
    cudaGetSymbolAddress((void**)&R,  g_R);

    detect_idx_kernel<<<1, 32>>>((const unsigned int*)lSi);

    // bottom MLP fused with embedding-bag blocks
    const int E1 = 4438, E2 = 4437, E3 = NEMB - 4438 - 4437;
    run_fused(x,  13,  bw1, 13,  bb1, h1, 512, 512, lSi, emb, 0,       E1);
    run_fused(h1, 512, bw2, 512, bb2, h2, 256, 256, lSi, emb, E1,      E2);
    run_fused(h2, 256, bw3, 256, bb3, T,  TROW, 64, lSi, emb, E1 + E2, E3);

    // dot interaction
    interact_kernel<<<BB, 128>>>();

    // top MLP
    run_fused(R,  RLD, tw1, 415, tb1, h1, 512, 512, lSi, emb, 0, 0);
    run_fused(h1, 512, tw2, 512, tb2, h2, 256, 256, lSi, emb, 0, 0);

    // final 256 -> 1 dot + sigmoid
    top3_kernel<<<BB / 8, 256>>>(tw3, tb3, out);
}